// round 16
// baseline (speedup 1.0000x reference)
#include <cuda_runtime.h>
#include <cuda_bf16.h>
#include <math.h>
#include <stdint.h>

// Problem dims
#define BB 16
#define LL 512
#define KK 48
#define EE 128
#define DD 384
#define HH 128

#define M_EDGES (BB*LL*KK)      // 393216
#define NTOK    (BB*LL)         // 8192

// Scratch (allocation-free: __device__ globals)
__device__ __nv_bfloat16 g_Eb [(size_t)M_EDGES * EE];   // ~100 MB (h_E in bf16)
__device__ __nv_bfloat16 g_T1b[(size_t)M_EDGES * DD];   // ~302 MB
__device__ __nv_bfloat16 g_fw1t[DD * EE];               // [n=384][k=128]
__device__ __nv_bfloat16 g_fw2t[DD * DD];               // [n=384][k=384]
__device__ float g_h [(size_t)NTOK * DD];
__device__ float g_dG[NTOK];

__device__ __forceinline__ float gelu_f(float x) {
    return 0.5f * x * (1.0f + erff(x * 0.70710678118654752f));
}

__device__ __forceinline__ uint32_t smem_u32(const void* p) {
    uint32_t a;
    asm("{ .reg .u64 t; cvta.to.shared.u64 t, %1; cvt.u32.u64 %0, t; }"
        : "=r"(a) : "l"(p));
    return a;
}
__device__ __forceinline__ void cp_async16(uint32_t dst, const void* src) {
    asm volatile("cp.async.cg.shared.global [%0], [%1], 16;"
                 :: "r"(dst), "l"(src) : "memory");
}
#define CP_COMMIT() asm volatile("cp.async.commit_group;" ::: "memory")
#define CP_WAIT(N)  asm volatile("cp.async.wait_group %0;" :: "n"(N) : "memory")

__device__ __forceinline__ void ldm_x4(uint32_t addr, uint32_t* r) {
    asm volatile("ldmatrix.sync.aligned.m8n8.x4.shared.b16 {%0,%1,%2,%3}, [%4];"
                 : "=r"(r[0]), "=r"(r[1]), "=r"(r[2]), "=r"(r[3]) : "r"(addr));
}
__device__ __forceinline__ void mma_bf16(float* c, const uint32_t* a, const uint32_t* b) {
    asm volatile(
        "mma.sync.aligned.m16n8k16.row.col.f32.bf16.bf16.f32 "
        "{%0,%1,%2,%3}, {%4,%5,%6,%7}, {%8,%9}, {%0,%1,%2,%3};"
        : "+f"(c[0]), "+f"(c[1]), "+f"(c[2]), "+f"(c[3])
        : "r"(a[0]), "r"(a[1]), "r"(a[2]), "r"(a[3]), "r"(b[0]), "r"(b[1]));
}

// ---------------------------------------------------------------------------
// K0a: convert h_E fp32 -> bf16; also zero g_h (needed by fused K2 atomics)
// ---------------------------------------------------------------------------
__global__ void __launch_bounds__(256)
convert_hE(const float* __restrict__ hE)
{
    size_t tid = (size_t)blockIdx.x * 256 + threadIdx.x;
    size_t i = tid * 4;
    if (i < (size_t)M_EDGES * EE) {
        float4 v = *(const float4*)&hE[i];
        __nv_bfloat162 p0(__float2bfloat16(v.x), __float2bfloat16(v.y));
        __nv_bfloat162 p1(__float2bfloat16(v.z), __float2bfloat16(v.w));
        uint2 w = { *(uint32_t*)&p0, *(uint32_t*)&p1 };
        *(uint2*)&g_Eb[i] = w;
    }
    if (i < (size_t)NTOK * DD) {
        *(float4*)&g_h[i] = make_float4(0.f, 0.f, 0.f, 0.f);
    }
}

// ---------------------------------------------------------------------------
// K0b: weight transpose to K-major [N][K] + bf16
// ---------------------------------------------------------------------------
__global__ void prep_weights(const float* __restrict__ fw1, const float* __restrict__ fw2)
{
    int i = blockIdx.x * 256 + threadIdx.x;
    if (i < DD * EE) {
        int n = i / EE, k = i % EE;
        g_fw1t[i] = __float2bfloat16(fw1[(size_t)k * DD + n]);
    }
    int j = i - DD * EE;
    if (j >= 0 && j < DD * DD) {
        int n = j / DD, k = j % DD;
        g_fw2t[j] = __float2bfloat16(fw2[(size_t)k * DD + n]);
    }
}

// ---------------------------------------------------------------------------
// bf16 HMMA GEMM, 128x128 block, BK=32, 2-stage cp.async, 8 warps (4x2).
// MODE 0: T1 = gelu(Eb @ fw1 + b)  -> stores bf16 T1
// MODE 1: fused CFConv: h[t,:] += sum_e gelu(T1@fw2+b)[e,:] * hV[b,Eidx[e],:]
//         (no T2 materialization; smem token accumulator + global atomics)
// ---------------------------------------------------------------------------
#define BK     32
#define ROWB   80                    // padded row stride in bytes (32 bf16 + 8 pad)
#define STAGEB (128 * ROWB)          // 10240 bytes per tile per stage

template<int KD, int MODE>
__global__ void __launch_bounds__(256)
gemm_ws(const float* __restrict__ bias,
        const float* __restrict__ hV, const int* __restrict__ Eidx)
{
    __shared__ __align__(128) char sA[2 * STAGEB];
    __shared__ __align__(128) char sB[2 * STAGEB];
    __shared__ int   sIdx[128];      // MODE 1: E_idx per edge row
    __shared__ float hacc[4][128];   // MODE 1: token-local accumulator

    const int tid  = threadIdx.x;
    const int wid  = tid >> 5;
    const int lane = tid & 31;
    const int wm   = wid & 3;          // warp row 0..3  (32 rows each)
    const int wn   = wid >> 2;         // warp col 0..1  (64 cols each)
    const int rowBase = blockIdx.y * 128;
    const int colBase = blockIdx.x * 128;

    const __nv_bfloat16* A = (MODE == 0) ? g_Eb  : g_T1b;
    const __nv_bfloat16* W = (MODE == 0) ? g_fw1t : g_fw2t;

    const uint32_t sAu = smem_u32(sA);
    const uint32_t sBu = smem_u32(sB);

    const __nv_bfloat16* Abase = A + (size_t)rowBase * KD;
    const __nv_bfloat16* Wbase = W + (size_t)colBase * KD;

    if (MODE == 1) {
        if (tid < 128) sIdx[tid] = Eidx[rowBase + tid];
        for (int i = tid; i < 4 * 128; i += 256) ((float*)hacc)[i] = 0.0f;
    }

    // Hoisted per-lane fragment offsets (byte offsets within a stage tile).
    const uint32_t aOff = (uint32_t)((wm * 32 + (lane & 15)) * ROWB + (lane >> 4) * 16);
    const int grp = lane >> 3, rr = lane & 7;
    const uint32_t bOff = (uint32_t)((wn * 64 + (grp >> 1) * 8 + rr) * ROWB + (grp & 1) * 16);

    // Hoisted cp.async lane addressing
    const int pr  = tid >> 2;                  // 0..63  (row block, x2 iters -> 128 rows)
    const int pcb = (tid & 3) * 16;            // byte col 0,16,32,48

    float acc[2][8][4];
#pragma unroll
    for (int mi = 0; mi < 2; ++mi)
#pragma unroll
        for (int ni = 0; ni < 8; ++ni)
#pragma unroll
            for (int q = 0; q < 4; ++q) acc[mi][ni][q] = 0.0f;

    constexpr int NK = KD / BK;

    auto prefetch = [&](int stage, int k0) {
#pragma unroll
        for (int it = 0; it < 2; ++it) {
            int r = pr + it * 64;              // 0..127
            cp_async16(sAu + stage * STAGEB + r * ROWB + pcb,
                       Abase + (size_t)r * KD + k0 + (pcb >> 1));
            cp_async16(sBu + stage * STAGEB + r * ROWB + pcb,
                       Wbase + (size_t)r * KD + k0 + (pcb >> 1));
        }
        CP_COMMIT();
    };

    prefetch(0, 0);

    for (int ks = 0; ks < NK; ++ks) {
        CP_WAIT(0);
        __syncthreads();   // all warps done reading buf (ks+1)&1 (iter ks-1) AND stage ks visible
        if (ks + 1 < NK) prefetch((ks + 1) & 1, (ks + 1) * BK);

        const uint32_t aT = sAu + (ks & 1) * STAGEB + aOff;
        const uint32_t bT = sBu + (ks & 1) * STAGEB + bOff;

#pragma unroll
        for (int ki = 0; ki < 2; ++ki) {
            uint32_t afr[2][4];
            ldm_x4(aT + ki * 32,              afr[0]);
            ldm_x4(aT + 16 * ROWB + ki * 32,  afr[1]);
#pragma unroll
            for (int nj = 0; nj < 4; ++nj) {
                uint32_t bfr[4];
                ldm_x4(bT + nj * (16 * ROWB) + ki * 32, bfr);
                mma_bf16(acc[0][nj * 2 + 0], afr[0], &bfr[0]);
                mma_bf16(acc[0][nj * 2 + 1], afr[0], &bfr[2]);
                mma_bf16(acc[1][nj * 2 + 0], afr[1], &bfr[0]);
                mma_bf16(acc[1][nj * 2 + 1], afr[1], &bfr[2]);
            }
        }
    }

    if (MODE == 0) {
        // Epilogue: bias + gelu, bf16 pair stores to T1
        __nv_bfloat16* C = g_T1b;
#pragma unroll
        for (int mi = 0; mi < 2; ++mi) {
            int r0 = rowBase + wm * 32 + mi * 16 + (lane >> 2);
#pragma unroll
            for (int ni = 0; ni < 8; ++ni) {
                int col = colBase + wn * 64 + ni * 8 + (lane & 3) * 2;
                float b0 = bias[col], b1 = bias[col + 1];
                __nv_bfloat162 p0(__float2bfloat16(gelu_f(acc[mi][ni][0] + b0)),
                                  __float2bfloat16(gelu_f(acc[mi][ni][1] + b1)));
                __nv_bfloat162 p1(__float2bfloat16(gelu_f(acc[mi][ni][2] + b0)),
                                  __float2bfloat16(gelu_f(acc[mi][ni][3] + b1)));
                *(__nv_bfloat162*)&C[(size_t)r0 * DD + col] = p0;
                *(__nv_bfloat162*)&C[(size_t)(r0 + 8) * DD + col] = p1;
            }
        }
    } else {
        // Fused epilogue: W = gelu(acc + bias); hacc[token][c] += W * hV_gather
        const int t0tok = rowBase / KK;
#pragma unroll
        for (int mi = 0; mi < 2; ++mi) {
#pragma unroll
            for (int half = 0; half < 2; ++half) {
                int r = wm * 32 + mi * 16 + (lane >> 2) + half * 8;
                int e = rowBase + r;
                int tl = e / KK - t0tok;                 // 0..3
                int b  = e / (LL * KK);
                const float* hVrow = hV + (size_t)b * LL * DD
                                        + (size_t)sIdx[r] * DD + colBase;
#pragma unroll
                for (int ni = 0; ni < 8; ++ni) {
                    int c = wn * 64 + ni * 8 + (lane & 3) * 2;
                    float v0 = gelu_f(acc[mi][ni][half * 2 + 0] + bias[colBase + c]);
                    float v1 = gelu_f(acc[mi][ni][half * 2 + 1] + bias[colBase + c + 1]);
                    float2 x = *(const float2*)&hVrow[c];
                    atomicAdd(&hacc[tl][c],     v0 * x.x);
                    atomicAdd(&hacc[tl][c + 1], v1 * x.y);
                }
            }
        }
        __syncthreads();
        for (int i = tid; i < 4 * 128; i += 256) {
            int t = t0tok + (i >> 7);
            if (t < NTOK)
                atomicAdd(&g_h[(size_t)t * DD + colBase + (i & 127)],
                          hacc[i >> 7][i & 127]);
        }
    }
}

// ---------------------------------------------------------------------------
// K4: head MLP, 16 tokens per block, 128 threads. float4 LDS + 4-wide unroll.
// ---------------------------------------------------------------------------
#define TOKS 16
__global__ void __launch_bounds__(128)
head_kernel(const float* __restrict__ hw1, const float* __restrict__ hb1,
            const float* __restrict__ hw2, const float* __restrict__ hb2,
            const float* __restrict__ hw3, const float* __restrict__ hb3,
            const float* __restrict__ mask)
{
    const int t0 = blockIdx.x * TOKS;
    const int j  = threadIdx.x;

    __shared__ float sh[TOKS][DD];
    __shared__ float g1[TOKS][HH];
    __shared__ float g2[TOKS][HH/2];

    for (int i = j * 4; i < TOKS * DD; i += 128 * 4)
        *(float4*)&((float*)sh)[i] = *(const float4*)&g_h[(size_t)t0 * DD + i];
    __syncthreads();

    // Stage 1: [TOKS,384] @ [384,128]
    {
        float acc[TOKS];
        const float bj = hb1[j];
#pragma unroll
        for (int tk = 0; tk < TOKS; ++tk) acc[tk] = bj;
#pragma unroll 2
        for (int dd = 0; dd < DD; dd += 4) {
            float w0 = hw1[(dd + 0) * HH + j];
            float w1 = hw1[(dd + 1) * HH + j];
            float w2 = hw1[(dd + 2) * HH + j];
            float w3 = hw1[(dd + 3) * HH + j];
#pragma unroll
            for (int tk = 0; tk < TOKS; ++tk) {
                float4 s = *(const float4*)&sh[tk][dd];
                acc[tk] = fmaf(s.x, w0, acc[tk]);
                acc[tk] = fmaf(s.y, w1, acc[tk]);
                acc[tk] = fmaf(s.z, w2, acc[tk]);
                acc[tk] = fmaf(s.w, w3, acc[tk]);
            }
        }
#pragma unroll
        for (int tk = 0; tk < TOKS; ++tk) g1[tk][j] = gelu_f(acc[tk]);
    }
    __syncthreads();

    // Stage 2: [TOKS,128] @ [128,64], fold in hw3 scale
    if (j < HH/2) {
        float acc[TOKS];
        const float bj = hb2[j];
#pragma unroll
        for (int tk = 0; tk < TOKS; ++tk) acc[tk] = bj;
#pragma unroll 2
        for (int i = 0; i < HH; i += 4) {
            float w0 = hw2[(i + 0) * (HH/2) + j];
            float w1 = hw2[(i + 1) * (HH/2) + j];
            float w2 = hw2[(i + 2) * (HH/2) + j];
            float w3 = hw2[(i + 3) * (HH/2) + j];
#pragma unroll
            for (int tk = 0; tk < TOKS; ++tk) {
                float4 s = *(const float4*)&g1[tk][i];
                acc[tk] = fmaf(s.x, w0, acc[tk]);
                acc[tk] = fmaf(s.y, w1, acc[tk]);
                acc[tk] = fmaf(s.z, w2, acc[tk]);
                acc[tk] = fmaf(s.w, w3, acc[tk]);
            }
        }
        const float w3s = hw3[j];
#pragma unroll
        for (int tk = 0; tk < TOKS; ++tk) g2[tk][j] = gelu_f(acc[tk]) * w3s;
    }
    __syncthreads();

    // Stage 3: reduce 64 per token
    if (j < TOKS) {
        float s = hb3[0];
#pragma unroll
        for (int i = 0; i < HH/2; ++i) s += g2[j][i];
        int t = t0 + j;
        g_dG[t] = s * mask[t];
    }
}

// ---------------------------------------------------------------------------
// K5: per-batch masked reduction
// ---------------------------------------------------------------------------
__global__ void __launch_bounds__(512)
finalize_kernel(const float* __restrict__ mask, float* __restrict__ out)
{
    const int b = blockIdx.x;
    const int j = threadIdx.x;

    float v = g_dG[b * LL + j];
    float m = mask[b * LL + j];

    __shared__ float sv[16], sm2[16];
#pragma unroll
    for (int off = 16; off; off >>= 1) {
        v += __shfl_down_sync(0xffffffffu, v, off);
        m += __shfl_down_sync(0xffffffffu, m, off);
    }
    if ((j & 31) == 0) { sv[j >> 5] = v; sm2[j >> 5] = m; }
    __syncthreads();
    if (j < 16) {
        v = sv[j]; m = sm2[j];
#pragma unroll
        for (int off = 8; off; off >>= 1) {
            v += __shfl_down_sync(0xffffu, v, off);
            m += __shfl_down_sync(0xffffu, m, off);
        }
        if (j == 0) out[b] = v / sqrtf(fmaxf(m, 1.0f));
    }
}

// ---------------------------------------------------------------------------
extern "C" void kernel_launch(void* const* d_in, const int* in_sizes, int n_in,
                              void* d_out, int out_size)
{
    const float* h_V  = (const float*)d_in[0];
    const float* h_E  = (const float*)d_in[1];
    const float* mask = (const float*)d_in[2];
    const float* fw1  = (const float*)d_in[3];
    const float* fb1  = (const float*)d_in[4];
    const float* fw2  = (const float*)d_in[5];
    const float* fb2  = (const float*)d_in[6];
    const float* hw1  = (const float*)d_in[7];
    const float* hb1  = (const float*)d_in[8];
    const float* hw2  = (const float*)d_in[9];
    const float* hb2  = (const float*)d_in[10];
    const float* hw3  = (const float*)d_in[11];
    const float* hb3  = (const float*)d_in[12];
    const int*   Eidx = (const int*)d_in[13];
    float* out = (float*)d_out;

    // K0a: h_E -> bf16, zero g_h
    convert_hE<<<(int)(((size_t)M_EDGES * EE / 4 + 255) / 256), 256>>>(h_E);
    // K0b: weight transpose + bf16
    prep_weights<<<(DD*EE + DD*DD + 255)/256, 256>>>(fw1, fw2);

    // K1: T1 = gelu(Eb @ fw1 + fb1)
    {
        dim3 grid(DD/128, M_EDGES/128);   // (3, 3072)
        gemm_ws<EE, 0><<<grid, 256>>>(fb1, nullptr, nullptr);
    }
    // K2 (fused): h += gather-weighted gelu(T1 @ fw2 + fb2)
    {
        dim3 grid(DD/128, M_EDGES/128);
        gemm_ws<DD, 1><<<grid, 256>>>(fb2, h_V, Eidx);
    }
    // K4: head MLP
    head_kernel<<<NTOK/TOKS, 128>>>(hw1, hb1, hw2, hb2, hw3, hb3, mask);
    // K5: batch reduce
    finalize_kernel<<<BB, LL>>>(mask, out);
}

// round 17
// speedup vs baseline: 2.0309x; 2.0309x over previous
#include <cuda_runtime.h>
#include <cuda_bf16.h>
#include <math.h>
#include <stdint.h>

// Problem dims
#define BB 16
#define LL 512
#define KK 48
#define EE 128
#define DD 384
#define HH 128

#define M_EDGES (BB*LL*KK)      // 393216
#define NTOK    (BB*LL)         // 8192

// Scratch (allocation-free: __device__ globals)
__device__ __nv_bfloat16 g_Eb [(size_t)M_EDGES * EE];   // ~100 MB (h_E in bf16)
__device__ __nv_bfloat16 g_T1b[(size_t)M_EDGES * DD];   // ~302 MB
__device__ __nv_bfloat16 g_fw1t[DD * EE];               // [n=384][k=128]
__device__ __nv_bfloat16 g_fw2t[DD * DD];               // [n=384][k=384]
__device__ float g_h [(size_t)NTOK * DD];
__device__ float g_dG[NTOK];

__device__ __forceinline__ float gelu_f(float x) {
    return 0.5f * x * (1.0f + erff(x * 0.70710678118654752f));
}

__device__ __forceinline__ uint32_t smem_u32(const void* p) {
    uint32_t a;
    asm("{ .reg .u64 t; cvta.to.shared.u64 t, %1; cvt.u32.u64 %0, t; }"
        : "=r"(a) : "l"(p));
    return a;
}
__device__ __forceinline__ void cp_async16(uint32_t dst, const void* src) {
    asm volatile("cp.async.cg.shared.global [%0], [%1], 16;"
                 :: "r"(dst), "l"(src) : "memory");
}
#define CP_COMMIT() asm volatile("cp.async.commit_group;" ::: "memory")
#define CP_WAIT(N)  asm volatile("cp.async.wait_group %0;" :: "n"(N) : "memory")

__device__ __forceinline__ void ldm_x4(uint32_t addr, uint32_t* r) {
    asm volatile("ldmatrix.sync.aligned.m8n8.x4.shared.b16 {%0,%1,%2,%3}, [%4];"
                 : "=r"(r[0]), "=r"(r[1]), "=r"(r[2]), "=r"(r[3]) : "r"(addr));
}
__device__ __forceinline__ void mma_bf16(float* c, const uint32_t* a, const uint32_t* b) {
    asm volatile(
        "mma.sync.aligned.m16n8k16.row.col.f32.bf16.bf16.f32 "
        "{%0,%1,%2,%3}, {%4,%5,%6,%7}, {%8,%9}, {%0,%1,%2,%3};"
        : "+f"(c[0]), "+f"(c[1]), "+f"(c[2]), "+f"(c[3])
        : "r"(a[0]), "r"(a[1]), "r"(a[2]), "r"(a[3]), "r"(b[0]), "r"(b[1]));
}

// ---------------------------------------------------------------------------
// K0a: convert h_E fp32 -> bf16; also zero g_h (needed by fused K2 atomics)
// ---------------------------------------------------------------------------
__global__ void __launch_bounds__(256)
convert_hE(const float* __restrict__ hE)
{
    size_t tid = (size_t)blockIdx.x * 256 + threadIdx.x;
    size_t i = tid * 4;
    if (i < (size_t)M_EDGES * EE) {
        float4 v = *(const float4*)&hE[i];
        __nv_bfloat162 p0(__float2bfloat16(v.x), __float2bfloat16(v.y));
        __nv_bfloat162 p1(__float2bfloat16(v.z), __float2bfloat16(v.w));
        uint2 w = { *(uint32_t*)&p0, *(uint32_t*)&p1 };
        *(uint2*)&g_Eb[i] = w;
    }
    if (i < (size_t)NTOK * DD) {
        *(float4*)&g_h[i] = make_float4(0.f, 0.f, 0.f, 0.f);
    }
}

// ---------------------------------------------------------------------------
// K0b: weight transpose to K-major [N][K] + bf16
// ---------------------------------------------------------------------------
__global__ void prep_weights(const float* __restrict__ fw1, const float* __restrict__ fw2)
{
    int i = blockIdx.x * 256 + threadIdx.x;
    if (i < DD * EE) {
        int n = i / EE, k = i % EE;
        g_fw1t[i] = __float2bfloat16(fw1[(size_t)k * DD + n]);
    }
    int j = i - DD * EE;
    if (j >= 0 && j < DD * DD) {
        int n = j / DD, k = j % DD;
        g_fw2t[j] = __float2bfloat16(fw2[(size_t)k * DD + n]);
    }
}

// ---------------------------------------------------------------------------
// bf16 HMMA GEMM, 128x128 block, BK=32, 2-stage cp.async, 8 warps (4x2).
// MODE 0: T1 = gelu(Eb @ fw1 + b)  -> stores bf16 T1
// MODE 1: fused CFConv: h[t,:] += sum_e gelu(T1@fw2+b)[e,:] * hV[b,Eidx[e],:]
//   Epilogue reduction is ATOMIC-LIGHT: each 16-row MMA group lies inside one
//   token (48 = 3*16), so row-sums are intra-warp shfl reductions; only lanes
//   0-3 issue one global atomicAdd per (mi,ni,col-pair).
// ---------------------------------------------------------------------------
#define BK     32
#define ROWB   80                    // padded row stride in bytes (32 bf16 + 8 pad)
#define STAGEB (128 * ROWB)          // 10240 bytes per tile per stage

template<int KD, int MODE>
__global__ void __launch_bounds__(256)
gemm_ws(const float* __restrict__ bias,
        const float* __restrict__ hV, const int* __restrict__ Eidx)
{
    __shared__ __align__(128) char sA[2 * STAGEB];
    __shared__ __align__(128) char sB[2 * STAGEB];
    __shared__ int sIdx[128];        // MODE 1: E_idx per edge row

    const int tid  = threadIdx.x;
    const int wid  = tid >> 5;
    const int lane = tid & 31;
    const int wm   = wid & 3;          // warp row 0..3  (32 rows each)
    const int wn   = wid >> 2;         // warp col 0..1  (64 cols each)
    const int rowBase = blockIdx.y * 128;
    const int colBase = blockIdx.x * 128;

    const __nv_bfloat16* A = (MODE == 0) ? g_Eb  : g_T1b;
    const __nv_bfloat16* W = (MODE == 0) ? g_fw1t : g_fw2t;

    const uint32_t sAu = smem_u32(sA);
    const uint32_t sBu = smem_u32(sB);

    const __nv_bfloat16* Abase = A + (size_t)rowBase * KD;
    const __nv_bfloat16* Wbase = W + (size_t)colBase * KD;

    if (MODE == 1) {
        if (tid < 128) sIdx[tid] = Eidx[rowBase + tid];
    }

    // Hoisted per-lane fragment offsets (byte offsets within a stage tile).
    const uint32_t aOff = (uint32_t)((wm * 32 + (lane & 15)) * ROWB + (lane >> 4) * 16);
    const int grp = lane >> 3, rr = lane & 7;
    const uint32_t bOff = (uint32_t)((wn * 64 + (grp >> 1) * 8 + rr) * ROWB + (grp & 1) * 16);

    // Hoisted cp.async lane addressing
    const int pr  = tid >> 2;                  // 0..63  (row block, x2 iters -> 128 rows)
    const int pcb = (tid & 3) * 16;            // byte col 0,16,32,48

    float acc[2][8][4];
#pragma unroll
    for (int mi = 0; mi < 2; ++mi)
#pragma unroll
        for (int ni = 0; ni < 8; ++ni)
#pragma unroll
            for (int q = 0; q < 4; ++q) acc[mi][ni][q] = 0.0f;

    constexpr int NK = KD / BK;

    auto prefetch = [&](int stage, int k0) {
#pragma unroll
        for (int it = 0; it < 2; ++it) {
            int r = pr + it * 64;              // 0..127
            cp_async16(sAu + stage * STAGEB + r * ROWB + pcb,
                       Abase + (size_t)r * KD + k0 + (pcb >> 1));
            cp_async16(sBu + stage * STAGEB + r * ROWB + pcb,
                       Wbase + (size_t)r * KD + k0 + (pcb >> 1));
        }
        CP_COMMIT();
    };

    prefetch(0, 0);

    for (int ks = 0; ks < NK; ++ks) {
        CP_WAIT(0);
        __syncthreads();   // all warps done reading buf (ks+1)&1 (iter ks-1) AND stage ks visible
        if (ks + 1 < NK) prefetch((ks + 1) & 1, (ks + 1) * BK);

        const uint32_t aT = sAu + (ks & 1) * STAGEB + aOff;
        const uint32_t bT = sBu + (ks & 1) * STAGEB + bOff;

#pragma unroll
        for (int ki = 0; ki < 2; ++ki) {
            uint32_t afr[2][4];
            ldm_x4(aT + ki * 32,              afr[0]);
            ldm_x4(aT + 16 * ROWB + ki * 32,  afr[1]);
#pragma unroll
            for (int nj = 0; nj < 4; ++nj) {
                uint32_t bfr[4];
                ldm_x4(bT + nj * (16 * ROWB) + ki * 32, bfr);
                mma_bf16(acc[0][nj * 2 + 0], afr[0], &bfr[0]);
                mma_bf16(acc[0][nj * 2 + 1], afr[0], &bfr[2]);
                mma_bf16(acc[1][nj * 2 + 0], afr[1], &bfr[0]);
                mma_bf16(acc[1][nj * 2 + 1], afr[1], &bfr[2]);
            }
        }
    }

    if (MODE == 0) {
        // Epilogue: bias + gelu, bf16 pair stores to T1
        __nv_bfloat16* C = g_T1b;
#pragma unroll
        for (int mi = 0; mi < 2; ++mi) {
            int r0 = rowBase + wm * 32 + mi * 16 + (lane >> 2);
#pragma unroll
            for (int ni = 0; ni < 8; ++ni) {
                int col = colBase + wn * 64 + ni * 8 + (lane & 3) * 2;
                float b0 = bias[col], b1 = bias[col + 1];
                __nv_bfloat162 p0(__float2bfloat16(gelu_f(acc[mi][ni][0] + b0)),
                                  __float2bfloat16(gelu_f(acc[mi][ni][1] + b1)));
                __nv_bfloat162 p1(__float2bfloat16(gelu_f(acc[mi][ni][2] + b0)),
                                  __float2bfloat16(gelu_f(acc[mi][ni][3] + b1)));
                *(__nv_bfloat162*)&C[(size_t)r0 * DD + col] = p0;
                *(__nv_bfloat162*)&C[(size_t)(r0 + 8) * DD + col] = p1;
            }
        }
    } else {
        // Fused epilogue, atomic-light:
        // 16-row group (wm,mi) -> single token. Per (mi,ni): thread combines
        // its two rows; shfl_xor over lane bits {4,8,16} sums the 8 lanes
        // sharing a column pair; lanes 0-3 atomicAdd the 16-row partial.
#pragma unroll
        for (int mi = 0; mi < 2; ++mi) {
            const int r16 = wm * 32 + mi * 16;       // group-local row base
            const int e16 = rowBase + r16;
            const int tok = e16 / KK;                // whole group same token
            const int b   = e16 / (LL * KK);
            const int r   = r16 + (lane >> 2);
            const float* hVrow0 = hV + (size_t)b * LL * DD + (size_t)sIdx[r] * DD + colBase;
            const float* hVrow1 = hV + (size_t)b * LL * DD + (size_t)sIdx[r + 8] * DD + colBase;
            float* hdst = g_h + (size_t)tok * DD + colBase;
#pragma unroll
            for (int ni = 0; ni < 8; ++ni) {
                int c = wn * 64 + ni * 8 + (lane & 3) * 2;
                float b0 = bias[colBase + c], b1 = bias[colBase + c + 1];
                float2 x0 = *(const float2*)&hVrow0[c];
                float2 x1 = *(const float2*)&hVrow1[c];
                float v0 = gelu_f(acc[mi][ni][0] + b0) * x0.x
                         + gelu_f(acc[mi][ni][2] + b0) * x1.x;
                float v1 = gelu_f(acc[mi][ni][1] + b1) * x0.y
                         + gelu_f(acc[mi][ni][3] + b1) * x1.y;
#pragma unroll
                for (int off = 4; off <= 16; off <<= 1) {
                    v0 += __shfl_xor_sync(0xffffffffu, v0, off);
                    v1 += __shfl_xor_sync(0xffffffffu, v1, off);
                }
                if (lane < 4) {
                    atomicAdd(&hdst[c],     v0);
                    atomicAdd(&hdst[c + 1], v1);
                }
            }
        }
    }
}

// ---------------------------------------------------------------------------
// K4: head MLP, 16 tokens per block, 128 threads. float4 LDS + 4-wide unroll.
// ---------------------------------------------------------------------------
#define TOKS 16
__global__ void __launch_bounds__(128)
head_kernel(const float* __restrict__ hw1, const float* __restrict__ hb1,
            const float* __restrict__ hw2, const float* __restrict__ hb2,
            const float* __restrict__ hw3, const float* __restrict__ hb3,
            const float* __restrict__ mask)
{
    const int t0 = blockIdx.x * TOKS;
    const int j  = threadIdx.x;

    __shared__ float sh[TOKS][DD];
    __shared__ float g1[TOKS][HH];
    __shared__ float g2[TOKS][HH/2];

    for (int i = j * 4; i < TOKS * DD; i += 128 * 4)
        *(float4*)&((float*)sh)[i] = *(const float4*)&g_h[(size_t)t0 * DD + i];
    __syncthreads();

    // Stage 1: [TOKS,384] @ [384,128]
    {
        float acc[TOKS];
        const float bj = hb1[j];
#pragma unroll
        for (int tk = 0; tk < TOKS; ++tk) acc[tk] = bj;
#pragma unroll 2
        for (int dd = 0; dd < DD; dd += 4) {
            float w0 = hw1[(dd + 0) * HH + j];
            float w1 = hw1[(dd + 1) * HH + j];
            float w2 = hw1[(dd + 2) * HH + j];
            float w3 = hw1[(dd + 3) * HH + j];
#pragma unroll
            for (int tk = 0; tk < TOKS; ++tk) {
                float4 s = *(const float4*)&sh[tk][dd];
                acc[tk] = fmaf(s.x, w0, acc[tk]);
                acc[tk] = fmaf(s.y, w1, acc[tk]);
                acc[tk] = fmaf(s.z, w2, acc[tk]);
                acc[tk] = fmaf(s.w, w3, acc[tk]);
            }
        }
#pragma unroll
        for (int tk = 0; tk < TOKS; ++tk) g1[tk][j] = gelu_f(acc[tk]);
    }
    __syncthreads();

    // Stage 2: [TOKS,128] @ [128,64], fold in hw3 scale
    if (j < HH/2) {
        float acc[TOKS];
        const float bj = hb2[j];
#pragma unroll
        for (int tk = 0; tk < TOKS; ++tk) acc[tk] = bj;
#pragma unroll 2
        for (int i = 0; i < HH; i += 4) {
            float w0 = hw2[(i + 0) * (HH/2) + j];
            float w1 = hw2[(i + 1) * (HH/2) + j];
            float w2 = hw2[(i + 2) * (HH/2) + j];
            float w3 = hw2[(i + 3) * (HH/2) + j];
#pragma unroll
            for (int tk = 0; tk < TOKS; ++tk) {
                float4 s = *(const float4*)&g1[tk][i];
                acc[tk] = fmaf(s.x, w0, acc[tk]);
                acc[tk] = fmaf(s.y, w1, acc[tk]);
                acc[tk] = fmaf(s.z, w2, acc[tk]);
                acc[tk] = fmaf(s.w, w3, acc[tk]);
            }
        }
        const float w3s = hw3[j];
#pragma unroll
        for (int tk = 0; tk < TOKS; ++tk) g2[tk][j] = gelu_f(acc[tk]) * w3s;
    }
    __syncthreads();

    // Stage 3: reduce 64 per token
    if (j < TOKS) {
        float s = hb3[0];
#pragma unroll
        for (int i = 0; i < HH/2; ++i) s += g2[j][i];
        int t = t0 + j;
        g_dG[t] = s * mask[t];
    }
}

// ---------------------------------------------------------------------------
// K5: per-batch masked reduction
// ---------------------------------------------------------------------------
__global__ void __launch_bounds__(512)
finalize_kernel(const float* __restrict__ mask, float* __restrict__ out)
{
    const int b = blockIdx.x;
    const int j = threadIdx.x;

    float v = g_dG[b * LL + j];
    float m = mask[b * LL + j];

    __shared__ float sv[16], sm2[16];
#pragma unroll
    for (int off = 16; off; off >>= 1) {
        v += __shfl_down_sync(0xffffffffu, v, off);
        m += __shfl_down_sync(0xffffffffu, m, off);
    }
    if ((j & 31) == 0) { sv[j >> 5] = v; sm2[j >> 5] = m; }
    __syncthreads();
    if (j < 16) {
        v = sv[j]; m = sm2[j];
#pragma unroll
        for (int off = 8; off; off >>= 1) {
            v += __shfl_down_sync(0xffffu, v, off);
            m += __shfl_down_sync(0xffffu, m, off);
        }
        if (j == 0) out[b] = v / sqrtf(fmaxf(m, 1.0f));
    }
}

// ---------------------------------------------------------------------------
extern "C" void kernel_launch(void* const* d_in, const int* in_sizes, int n_in,
                              void* d_out, int out_size)
{
    const float* h_V  = (const float*)d_in[0];
    const float* h_E  = (const float*)d_in[1];
    const float* mask = (const float*)d_in[2];
    const float* fw1  = (const float*)d_in[3];
    const float* fb1  = (const float*)d_in[4];
    const float* fw2  = (const float*)d_in[5];
    const float* fb2  = (const float*)d_in[6];
    const float* hw1  = (const float*)d_in[7];
    const float* hb1  = (const float*)d_in[8];
    const float* hw2  = (const float*)d_in[9];
    const float* hb2  = (const float*)d_in[10];
    const float* hw3  = (const float*)d_in[11];
    const float* hb3  = (const float*)d_in[12];
    const int*   Eidx = (const int*)d_in[13];
    float* out = (float*)d_out;

    // K0a: h_E -> bf16, zero g_h
    convert_hE<<<(int)(((size_t)M_EDGES * EE / 4 + 255) / 256), 256>>>(h_E);
    // K0b: weight transpose + bf16
    prep_weights<<<(DD*EE + DD*DD + 255)/256, 256>>>(fw1, fw2);

    // K1: T1 = gelu(Eb @ fw1 + fb1)
    {
        dim3 grid(DD/128, M_EDGES/128);   // (3, 3072)
        gemm_ws<EE, 0><<<grid, 256>>>(fb1, nullptr, nullptr);
    }
    // K2 (fused): h += gather-weighted gelu(T1 @ fw2 + fb2)
    {
        dim3 grid(DD/128, M_EDGES/128);
        gemm_ws<DD, 1><<<grid, 256>>>(fb2, h_V, Eidx);
    }
    // K4: head MLP
    head_kernel<<<NTOK/TOKS, 128>>>(hw1, hb1, hw2, hb2, hw3, hb3, mask);
    // K5: batch reduce
    finalize_kernel<<<BB, LL>>>(mask, out);
}